// round 1
// baseline (speedup 1.0000x reference)
#include <cuda_runtime.h>
#include <cstdint>

// Shapes
#define Bsz 8
#define Lq 1024
#define Fq 128
#define Dq 256
#define DI 512
#define Nst 32
#define Kcv 4
#define Rq 16
#define NC 2
#define ROWS (Bsz*Lq)   // 8192

// ---------------- scratch (static device globals; no allocations) ----------------
__device__ __align__(16) float g_t0[ROWS*Dq];       // fc1 pre-LN
__device__ __align__(16) float g_u[ROWS*Dq];        // LN+relu out
__device__ __align__(16) float g_xz[ROWS*2*DI];     // in_proj out (xi_raw | z)
__device__ __align__(16) float g_xi[ROWS*DI];       // conv+silu out
__device__ __align__(16) float g_dbc[ROWS*80];      // x_proj out (dt|B|C)
__device__ __align__(16) float g_delta[ROWS*DI];    // softplus(dt_proj)
__device__ __align__(16) float g_y[ROWS*DI];        // scan out, gated
__device__ __align__(16) float g_o[ROWS*Dq];        // out_proj out

// ---------------- generic tiled SGEMM: C(M,N) = A(M,K) * B(N,K)^T (+bias, EPI) ----
// EPI: 0 = none, 1 = softplus
#define BM 64
#define BN 64
#define BKT 16

template<int EPI>
__global__ __launch_bounds__(256) void gemm_tn(
    const float* __restrict__ A, int lda,
    const float* __restrict__ Bw,         // (N,K) row-major, ldb = K
    const float* __restrict__ bias,       // length N or nullptr
    float* __restrict__ C, int ldc,
    int M, int N, int K)
{
    __shared__ __align__(16) float As[BKT][BM];
    __shared__ __align__(16) float Bs[BKT][BN];
    const int tid = threadIdx.x;
    const int tx = tid & 15, ty = tid >> 4;
    const int m0 = blockIdx.y * BM, n0 = blockIdx.x * BN;

    const int arow = tid >> 2;            // 0..63
    const int ac4  = (tid & 3) * 4;       // 0,4,8,12
    const float* Aptr = A + (size_t)(m0 + arow) * lda + ac4;
    const float* Bptr = Bw + (size_t)(n0 + arow) * K + ac4;
    const bool bvalid = (n0 + arow) < N;

    float acc[4][4];
    #pragma unroll
    for (int i = 0; i < 4; i++)
        #pragma unroll
        for (int j = 0; j < 4; j++) acc[i][j] = 0.f;

    for (int k0 = 0; k0 < K; k0 += BKT) {
        float4 av = *(const float4*)(Aptr + k0);
        float4 bv = bvalid ? *(const float4*)(Bptr + k0) : make_float4(0.f,0.f,0.f,0.f);
        As[ac4+0][arow] = av.x; As[ac4+1][arow] = av.y;
        As[ac4+2][arow] = av.z; As[ac4+3][arow] = av.w;
        Bs[ac4+0][arow] = bv.x; Bs[ac4+1][arow] = bv.y;
        Bs[ac4+2][arow] = bv.z; Bs[ac4+3][arow] = bv.w;
        __syncthreads();
        #pragma unroll
        for (int k = 0; k < BKT; k++) {
            float4 a = *(const float4*)&As[k][ty*4];
            float4 b = *(const float4*)&Bs[k][tx*4];
            float ar[4] = {a.x, a.y, a.z, a.w};
            float br[4] = {b.x, b.y, b.z, b.w};
            #pragma unroll
            for (int i = 0; i < 4; i++)
                #pragma unroll
                for (int j = 0; j < 4; j++)
                    acc[i][j] += ar[i] * br[j];
        }
        __syncthreads();
    }

    #pragma unroll
    for (int i = 0; i < 4; i++) {
        const int row = m0 + ty*4 + i;
        #pragma unroll
        for (int j = 0; j < 4; j++) {
            const int col = n0 + tx*4 + j;
            if (col < N) {
                float v = acc[i][j] + (bias ? __ldg(bias + col) : 0.f);
                if (EPI == 1) v = fmaxf(v, 0.f) + log1pf(__expf(-fabsf(v)));
                C[(size_t)row * ldc + col] = v;
            }
        }
    }
}

// ---------------- LayerNorm (+relu) over D=256, block per row -----------------
__inline__ __device__ float warpSum(float v) {
    #pragma unroll
    for (int o = 16; o; o >>= 1) v += __shfl_xor_sync(0xffffffffu, v, o);
    return v;
}

__global__ __launch_bounds__(256) void ln_relu_kernel(
    const float* __restrict__ in, const float* __restrict__ gam,
    const float* __restrict__ bet, float* __restrict__ out)
{
    const int row = blockIdx.x, tid = threadIdx.x;
    const float v = in[(size_t)row * Dq + tid];
    float s = warpSum(v);
    float q = warpSum(v * v);
    __shared__ float ss[8], sq[8];
    if ((tid & 31) == 0) { ss[tid >> 5] = s; sq[tid >> 5] = q; }
    __syncthreads();
    float tot = 0.f, totq = 0.f;
    #pragma unroll
    for (int i = 0; i < 8; i++) { tot += ss[i]; totq += sq[i]; }
    const float mu  = tot * (1.f / Dq);
    const float var = totq * (1.f / Dq) - mu * mu;
    const float r   = rsqrtf(var + 1e-5f);
    float o = (v - mu) * r * gam[tid] + bet[tid];
    out[(size_t)row * Dq + tid] = fmaxf(o, 0.f);
}

// ---------------- depthwise causal conv K=4 + silu ----------------------------
__global__ __launch_bounds__(256) void conv_silu_kernel(
    const float* __restrict__ xz, const float* __restrict__ cw,
    const float* __restrict__ cb, float* __restrict__ xi)
{
    const int idx = blockIdx.x * blockDim.x + threadIdx.x; // < ROWS*DI
    const int d = idx & (DI - 1);
    const int row = idx >> 9;
    const int t = row & (Lq - 1);
    const int b = row >> 10;
    float acc = cb[d];
    const float* base = xz + (size_t)b * Lq * (2*DI) + d;
    #pragma unroll
    for (int k = 0; k < Kcv; k++) {
        int tt = t - (Kcv - 1) + k;
        if (tt >= 0) acc += cw[d * Kcv + k] * base[(size_t)tt * (2*DI)];
    }
    // silu
    xi[idx] = acc / (1.f + __expf(-acc));
}

// ---------------- selective scan: 4 channels/warp, 8 lanes/channel ------------
__global__ __launch_bounds__(256) void scan_kernel(
    const float* __restrict__ delta, const float* __restrict__ dbc,
    const float* __restrict__ xi, const float* __restrict__ xz,
    const float* __restrict__ A_log, const float* __restrict__ D_param,
    float* __restrict__ y)
{
    const int w = (blockIdx.x * blockDim.x + threadIdx.x) >> 5; // 0..1023
    const int lane = threadIdx.x & 31;
    const int b  = w >> 7;          // 128 d-groups per batch
    const int dg = w & 127;
    const int li = lane & 7;        // lane within channel (8 lanes)
    const int ci = lane >> 3;       // channel within warp (4)
    const int d  = dg * 4 + ci;

    const float LOG2E = 1.4426950408889634f;
    float Ac[4], h[4];
    #pragma unroll
    for (int j = 0; j < 4; j++) {
        Ac[j] = -__expf(A_log[d * Nst + li * 4 + j]) * LOG2E;
        h[j] = 0.f;
    }
    const float Dp = D_param[d];

    const size_t rowbase = (size_t)b * Lq;
    for (int t = 0; t < Lq; t++) {
        const size_t r = rowbase + t;
        const float dv = __ldg(delta + r * DI + d);
        const float xv = __ldg(xi + r * DI + d);
        const float zv = __ldg(xz + r * (2*DI) + DI + d);
        const float4 Bv = *(const float4*)(dbc + r * 80 + Rq + li * 4);
        const float4 Cv = *(const float4*)(dbc + r * 80 + Rq + Nst + li * 4);
        const float dx = dv * xv;
        float acc;
        h[0] = exp2f(dv * Ac[0]) * h[0] + dx * Bv.x;
        h[1] = exp2f(dv * Ac[1]) * h[1] + dx * Bv.y;
        h[2] = exp2f(dv * Ac[2]) * h[2] + dx * Bv.z;
        h[3] = exp2f(dv * Ac[3]) * h[3] + dx * Bv.w;
        acc  = h[0] * Cv.x + h[1] * Cv.y + h[2] * Cv.z + h[3] * Cv.w;
        acc += __shfl_xor_sync(0xffffffffu, acc, 4);
        acc += __shfl_xor_sync(0xffffffffu, acc, 2);
        acc += __shfl_xor_sync(0xffffffffu, acc, 1);
        if (li == 0) {
            const float yv = acc + xv * Dp;
            const float sz = zv / (1.f + __expf(-zv));
            y[r * DI + d] = yv * sz;
        }
    }
}

// ---------------- final head: logits = o @ W_out^T + b_out --------------------
__global__ __launch_bounds__(256) void head_kernel(
    const float* __restrict__ o, const float* __restrict__ Wout,
    const float* __restrict__ bout, float* __restrict__ out)
{
    const int w = (blockIdx.x * blockDim.x + threadIdx.x) >> 5; // row
    const int lane = threadIdx.x & 31;
    float a0 = 0.f, a1 = 0.f;
    const float* orow = o + (size_t)w * Dq;
    #pragma unroll
    for (int k = lane; k < Dq; k += 32) {
        const float ov = orow[k];
        a0 += ov * Wout[k];
        a1 += ov * Wout[Dq + k];
    }
    a0 = warpSum(a0);
    a1 = warpSum(a1);
    if (lane == 0) {
        out[(size_t)w * NC + 0] = a0 + bout[0];
        out[(size_t)w * NC + 1] = a1 + bout[1];
    }
}

// ---------------- launch ------------------------------------------------------
static float* symAddr(const void* symbol) {
    void* p = nullptr;
    cudaGetSymbolAddress(&p, symbol);
    return (float*)p;
}

extern "C" void kernel_launch(void* const* d_in, const int* in_sizes, int n_in,
                              void* d_out, int out_size)
{
    const float* x         = (const float*)d_in[0];
    const float* W1        = (const float*)d_in[1];
    const float* b1        = (const float*)d_in[2];
    const float* ln_g      = (const float*)d_in[3];
    const float* ln_b      = (const float*)d_in[4];
    const float* in_proj_w = (const float*)d_in[5];
    const float* conv_w    = (const float*)d_in[6];
    const float* conv_b    = (const float*)d_in[7];
    const float* x_proj_w  = (const float*)d_in[8];
    const float* dt_proj_w = (const float*)d_in[9];
    const float* dt_proj_b = (const float*)d_in[10];
    const float* A_log     = (const float*)d_in[11];
    const float* D_param   = (const float*)d_in[12];
    const float* out_proj_w= (const float*)d_in[13];
    const float* W_out     = (const float*)d_in[14];
    const float* b_out     = (const float*)d_in[15];
    float* out = (float*)d_out;

    float* t0    = symAddr(g_t0);
    float* u     = symAddr(g_u);
    float* xz    = symAddr(g_xz);
    float* xi    = symAddr(g_xi);
    float* dbc   = symAddr(g_dbc);
    float* delta = symAddr(g_delta);
    float* y     = symAddr(g_y);
    float* o     = symAddr(g_o);

    // 1) fc1: t0 = x @ W1^T + b1   (M=8192, N=256, K=128)
    gemm_tn<0><<<dim3(Dq/BN, ROWS/BM), 256>>>(x, Fq, W1, b1, t0, Dq, ROWS, Dq, Fq);
    // 2) LN + relu -> u
    ln_relu_kernel<<<ROWS, Dq>>>(t0, ln_g, ln_b, u);
    // 3) in_proj: xz = u @ in_proj_w^T   (N=1024, K=256)
    gemm_tn<0><<<dim3((2*DI)/BN, ROWS/BM), 256>>>(u, Dq, in_proj_w, nullptr, xz, 2*DI, ROWS, 2*DI, Dq);
    // 4) depthwise conv + silu -> xi
    conv_silu_kernel<<<(ROWS*DI)/256, 256>>>(xz, conv_w, conv_b, xi);
    // 5) x_proj: dbc = xi @ x_proj_w^T   (N=80, K=512)
    gemm_tn<0><<<dim3(2, ROWS/BM), 256>>>(xi, DI, x_proj_w, nullptr, dbc, 80, ROWS, 80, DI);
    // 6) dt_proj + softplus: delta = softplus(dbc[:, :16] @ dt_proj_w^T + b)  (N=512, K=16, lda=80)
    gemm_tn<1><<<dim3(DI/BN, ROWS/BM), 256>>>(dbc, 80, dt_proj_w, dt_proj_b, delta, DI, ROWS, DI, Rq);
    // 7) selective scan (fused +xi*D and *silu(z)) -> y
    scan_kernel<<<128, 256>>>(delta, dbc, xi, xz, A_log, D_param, y);
    // 8) out_proj: o = y @ out_proj_w^T  (N=256, K=512)
    gemm_tn<0><<<dim3(Dq/BN, ROWS/BM), 256>>>(y, DI, out_proj_w, nullptr, o, Dq, ROWS, Dq, DI);
    // 9) head -> logits
    head_kernel<<<ROWS/8, 256>>>(o, W_out, b_out, out);
}

// round 2
// speedup vs baseline: 1.4190x; 1.4190x over previous
#include <cuda_runtime.h>
#include <cstdint>

// Shapes
#define Bsz 8
#define Lq 1024
#define Fq 128
#define Dq 256
#define DI 512
#define Nst 32
#define Kcv 4
#define Rq 16
#define NC 2
#define ROWS (Bsz*Lq)   // 8192

// ---------------- scratch (static device globals; no allocations) ----------------
__device__ __align__(16) float g_t0[ROWS*Dq];       // fc1 pre-LN
__device__ __align__(16) float g_u[ROWS*Dq];        // LN+relu out
__device__ __align__(16) float g_xz[ROWS*2*DI];     // in_proj out (xi_raw | z)
__device__ __align__(16) float g_xi[ROWS*DI];       // conv+silu out
__device__ __align__(16) float g_dbc[ROWS*80];      // x_proj out (dt|B|C)
__device__ __align__(16) float g_delta[ROWS*DI];    // softplus(dt_proj)
__device__ __align__(16) float g_y[ROWS*DI];        // scan out, gated
__device__ __align__(16) float g_o[ROWS*Dq];        // out_proj out

// =======================================================================
// SGEMM: C(M,N) = A(M,K) * B(N,K)^T (+bias, EPI)  — 128x128x8, 8x8/thread,
// double-buffered shared memory.  M % 128 == 0, K % 8 == 0, N arbitrary.
// EPI: 0 none, 1 softplus
// =======================================================================
template<int EPI>
__global__ __launch_bounds__(256) void sgemm128(
    const float* __restrict__ A, int lda,
    const float* __restrict__ Bw,   // (N,K) row-major
    const float* __restrict__ bias, // length N or nullptr
    float* __restrict__ C, int ldc,
    int M, int N, int K)
{
    __shared__ __align__(16) float As[2][8][132];
    __shared__ __align__(16) float Bs[2][8][132];

    const int tid = threadIdx.x;
    const int m0 = blockIdx.y * 128;
    const int n0 = blockIdx.x * 128;

    // global-load assignment: 256 threads, one float4 each per tile
    const int lrow = tid >> 1;           // 0..127
    const int lk   = (tid & 1) * 4;      // 0 or 4
    const float* Ap = A + (size_t)(m0 + lrow) * lda + lk;
    const bool  bval = (n0 + lrow) < N;
    const float* Bp = Bw + (size_t)(n0 + lrow) * K + lk;

    // compute assignment: 16x16 threads, 8x8 each
    const int tx = tid & 15;
    const int ty = tid >> 4;

    float acc[8][8];
    #pragma unroll
    for (int i = 0; i < 8; i++)
        #pragma unroll
        for (int j = 0; j < 8; j++) acc[i][j] = 0.f;

    // preload tile 0
    {
        float4 av = *(const float4*)Ap;
        float4 bv = bval ? *(const float4*)Bp : make_float4(0.f,0.f,0.f,0.f);
        As[0][lk+0][lrow] = av.x; As[0][lk+1][lrow] = av.y;
        As[0][lk+2][lrow] = av.z; As[0][lk+3][lrow] = av.w;
        Bs[0][lk+0][lrow] = bv.x; Bs[0][lk+1][lrow] = bv.y;
        Bs[0][lk+2][lrow] = bv.z; Bs[0][lk+3][lrow] = bv.w;
    }
    __syncthreads();

    int buf = 0;
    for (int k0 = 8; k0 <= K; k0 += 8) {
        float4 an, bn;
        const bool more = (k0 < K);
        if (more) {
            an = *(const float4*)(Ap + k0);
            bn = bval ? *(const float4*)(Bp + k0) : make_float4(0.f,0.f,0.f,0.f);
        }
        #pragma unroll
        for (int k = 0; k < 8; k++) {
            float4 a0 = *(const float4*)&As[buf][k][ty*8];
            float4 a1 = *(const float4*)&As[buf][k][ty*8+4];
            float4 b0 = *(const float4*)&Bs[buf][k][tx*8];
            float4 b1 = *(const float4*)&Bs[buf][k][tx*8+4];
            float ar[8] = {a0.x,a0.y,a0.z,a0.w,a1.x,a1.y,a1.z,a1.w};
            float br[8] = {b0.x,b0.y,b0.z,b0.w,b1.x,b1.y,b1.z,b1.w};
            #pragma unroll
            for (int i = 0; i < 8; i++)
                #pragma unroll
                for (int j = 0; j < 8; j++)
                    acc[i][j] += ar[i] * br[j];
        }
        if (more) {
            buf ^= 1;
            As[buf][lk+0][lrow] = an.x; As[buf][lk+1][lrow] = an.y;
            As[buf][lk+2][lrow] = an.z; As[buf][lk+3][lrow] = an.w;
            Bs[buf][lk+0][lrow] = bn.x; Bs[buf][lk+1][lrow] = bn.y;
            Bs[buf][lk+2][lrow] = bn.z; Bs[buf][lk+3][lrow] = bn.w;
            __syncthreads();
        }
    }

    // epilogue
    #pragma unroll
    for (int i = 0; i < 8; i++) {
        const int row = m0 + ty*8 + i;
        #pragma unroll
        for (int j = 0; j < 8; j++) {
            const int col = n0 + tx*8 + j;
            if (col < N) {
                float v = acc[i][j] + (bias ? __ldg(bias + col) : 0.f);
                if (EPI == 1) v = fmaxf(v, 0.f) + log1pf(__expf(-fabsf(v)));
                C[(size_t)row * ldc + col] = v;
            }
        }
    }
}

// ---------------- LayerNorm (+relu) over D=256, block per row -----------------
__inline__ __device__ float warpSum(float v) {
    #pragma unroll
    for (int o = 16; o; o >>= 1) v += __shfl_xor_sync(0xffffffffu, v, o);
    return v;
}

__global__ __launch_bounds__(256) void ln_relu_kernel(
    const float* __restrict__ in, const float* __restrict__ gam,
    const float* __restrict__ bet, float* __restrict__ out)
{
    const int row = blockIdx.x, tid = threadIdx.x;
    const float v = in[(size_t)row * Dq + tid];
    float s = warpSum(v);
    float q = warpSum(v * v);
    __shared__ float ss[8], sq[8];
    if ((tid & 31) == 0) { ss[tid >> 5] = s; sq[tid >> 5] = q; }
    __syncthreads();
    float tot = 0.f, totq = 0.f;
    #pragma unroll
    for (int i = 0; i < 8; i++) { tot += ss[i]; totq += sq[i]; }
    const float mu  = tot * (1.f / Dq);
    const float var = totq * (1.f / Dq) - mu * mu;
    const float r   = rsqrtf(var + 1e-5f);
    float o = (v - mu) * r * gam[tid] + bet[tid];
    out[(size_t)row * Dq + tid] = fmaxf(o, 0.f);
}

// ---------------- depthwise causal conv K=4 + silu, 4 timesteps/thread --------
__global__ __launch_bounds__(256) void conv_silu_kernel(
    const float* __restrict__ xz, const float* __restrict__ cw,
    const float* __restrict__ cb, float* __restrict__ xi)
{
    const int idx = blockIdx.x * blockDim.x + threadIdx.x; // < ROWS*DI/4
    const int d = idx & (DI - 1);
    const int rg = idx >> 9;
    const int t0 = (rg & 255) * 4;
    const int b  = rg >> 8;

    const float w0 = __ldg(cw + d*Kcv + 0);
    const float w1 = __ldg(cw + d*Kcv + 1);
    const float w2 = __ldg(cw + d*Kcv + 2);
    const float w3 = __ldg(cw + d*Kcv + 3);
    const float bb = __ldg(cb + d);

    const float* base = xz + (size_t)b * Lq * (2*DI) + d;
    float v[7];
    #pragma unroll
    for (int k = 0; k < 7; k++) {
        const int tt = t0 - 3 + k;
        v[k] = (tt >= 0) ? base[(size_t)tt * (2*DI)] : 0.f;
    }
    float* outp = xi + ((size_t)b * Lq + t0) * DI + d;
    #pragma unroll
    for (int j = 0; j < 4; j++) {
        float a = bb + w0*v[j] + w1*v[j+1] + w2*v[j+2] + w3*v[j+3];
        outp[(size_t)j * DI] = a / (1.f + __expf(-a));
    }
}

// ---------------- selective scan: 4 channels/warp, 8 lanes/channel ------------
__global__ __launch_bounds__(256) void scan_kernel(
    const float* __restrict__ delta, const float* __restrict__ dbc,
    const float* __restrict__ xi, const float* __restrict__ xz,
    const float* __restrict__ A_log, const float* __restrict__ D_param,
    float* __restrict__ y)
{
    const int w = (blockIdx.x * blockDim.x + threadIdx.x) >> 5; // 0..1023
    const int lane = threadIdx.x & 31;
    const int b  = w >> 7;          // 128 d-groups per batch
    const int dg = w & 127;
    const int li = lane & 7;        // lane within channel (8 lanes)
    const int ci = lane >> 3;       // channel within warp (4)
    const int d  = dg * 4 + ci;

    const float LOG2E = 1.4426950408889634f;
    float Ac[4], h[4];
    #pragma unroll
    for (int j = 0; j < 4; j++) {
        Ac[j] = -__expf(A_log[d * Nst + li * 4 + j]) * LOG2E;
        h[j] = 0.f;
    }
    const float Dp = D_param[d];

    const size_t rowbase = (size_t)b * Lq;
    for (int t = 0; t < Lq; t++) {
        const size_t r = rowbase + t;
        const float dv = __ldg(delta + r * DI + d);
        const float xv = __ldg(xi + r * DI + d);
        const float zv = __ldg(xz + r * (2*DI) + DI + d);
        const float4 Bv = *(const float4*)(dbc + r * 80 + Rq + li * 4);
        const float4 Cv = *(const float4*)(dbc + r * 80 + Rq + Nst + li * 4);
        const float dx = dv * xv;
        float acc;
        h[0] = exp2f(dv * Ac[0]) * h[0] + dx * Bv.x;
        h[1] = exp2f(dv * Ac[1]) * h[1] + dx * Bv.y;
        h[2] = exp2f(dv * Ac[2]) * h[2] + dx * Bv.z;
        h[3] = exp2f(dv * Ac[3]) * h[3] + dx * Bv.w;
        acc  = h[0] * Cv.x + h[1] * Cv.y + h[2] * Cv.z + h[3] * Cv.w;
        acc += __shfl_xor_sync(0xffffffffu, acc, 4);
        acc += __shfl_xor_sync(0xffffffffu, acc, 2);
        acc += __shfl_xor_sync(0xffffffffu, acc, 1);
        if (li == 0) {
            const float yv = acc + xv * Dp;
            const float sz = zv / (1.f + __expf(-zv));
            y[r * DI + d] = yv * sz;
        }
    }
}

// ---------------- final head: logits = o @ W_out^T + b_out --------------------
__global__ __launch_bounds__(256) void head_kernel(
    const float* __restrict__ o, const float* __restrict__ Wout,
    const float* __restrict__ bout, float* __restrict__ out)
{
    const int w = (blockIdx.x * blockDim.x + threadIdx.x) >> 5; // row
    const int lane = threadIdx.x & 31;
    float a0 = 0.f, a1 = 0.f;
    const float* orow = o + (size_t)w * Dq;
    #pragma unroll
    for (int k = lane; k < Dq; k += 32) {
        const float ov = orow[k];
        a0 += ov * Wout[k];
        a1 += ov * Wout[Dq + k];
    }
    a0 = warpSum(a0);
    a1 = warpSum(a1);
    if (lane == 0) {
        out[(size_t)w * NC + 0] = a0 + bout[0];
        out[(size_t)w * NC + 1] = a1 + bout[1];
    }
}

// ---------------- launch ------------------------------------------------------
static float* symAddr(const void* symbol) {
    void* p = nullptr;
    cudaGetSymbolAddress(&p, symbol);
    return (float*)p;
}

extern "C" void kernel_launch(void* const* d_in, const int* in_sizes, int n_in,
                              void* d_out, int out_size)
{
    const float* x         = (const float*)d_in[0];
    const float* W1        = (const float*)d_in[1];
    const float* b1        = (const float*)d_in[2];
    const float* ln_g      = (const float*)d_in[3];
    const float* ln_b      = (const float*)d_in[4];
    const float* in_proj_w = (const float*)d_in[5];
    const float* conv_w    = (const float*)d_in[6];
    const float* conv_b    = (const float*)d_in[7];
    const float* x_proj_w  = (const float*)d_in[8];
    const float* dt_proj_w = (const float*)d_in[9];
    const float* dt_proj_b = (const float*)d_in[10];
    const float* A_log     = (const float*)d_in[11];
    const float* D_param   = (const float*)d_in[12];
    const float* out_proj_w= (const float*)d_in[13];
    const float* W_out     = (const float*)d_in[14];
    const float* b_out     = (const float*)d_in[15];
    float* out = (float*)d_out;

    float* t0    = symAddr(g_t0);
    float* u     = symAddr(g_u);
    float* xz    = symAddr(g_xz);
    float* xi    = symAddr(g_xi);
    float* dbc   = symAddr(g_dbc);
    float* delta = symAddr(g_delta);
    float* y     = symAddr(g_y);
    float* o     = symAddr(g_o);

    // 1) fc1: t0 = x @ W1^T + b1   (M=8192, N=256, K=128)
    sgemm128<0><<<dim3(Dq/128, ROWS/128), 256>>>(x, Fq, W1, b1, t0, Dq, ROWS, Dq, Fq);
    // 2) LN + relu -> u
    ln_relu_kernel<<<ROWS, Dq>>>(t0, ln_g, ln_b, u);
    // 3) in_proj: xz = u @ in_proj_w^T   (N=1024, K=256)
    sgemm128<0><<<dim3((2*DI)/128, ROWS/128), 256>>>(u, Dq, in_proj_w, nullptr, xz, 2*DI, ROWS, 2*DI, Dq);
    // 4) depthwise conv + silu -> xi
    conv_silu_kernel<<<(ROWS*DI/4)/256, 256>>>(xz, conv_w, conv_b, xi);
    // 5) x_proj: dbc = xi @ x_proj_w^T   (N=80, K=512)
    sgemm128<0><<<dim3(1, ROWS/128), 256>>>(xi, DI, x_proj_w, nullptr, dbc, 80, ROWS, 80, DI);
    // 6) dt_proj + softplus: delta = softplus(dbc[:, :16] @ dt_proj_w^T + b)  (N=512, K=16)
    sgemm128<1><<<dim3(DI/128, ROWS/128), 256>>>(dbc, 80, dt_proj_w, dt_proj_b, delta, DI, ROWS, DI, Rq);
    // 7) selective scan (fused +xi*D and *silu(z)) -> y
    scan_kernel<<<128, 256>>>(delta, dbc, xi, xz, A_log, D_param, y);
    // 8) out_proj: o = y @ out_proj_w^T  (N=256, K=512)
    sgemm128<0><<<dim3(Dq/128, ROWS/128), 256>>>(y, DI, out_proj_w, nullptr, o, Dq, ROWS, Dq, DI);
    // 9) head -> logits
    head_kernel<<<ROWS/8, 256>>>(o, W_out, b_out, out);
}

// round 3
// speedup vs baseline: 2.5539x; 1.7998x over previous
#include <cuda_runtime.h>
#include <cstdint>

// Shapes
#define Bsz 8
#define Lq 1024
#define Fq 128
#define Dq 256
#define DI 512
#define Nst 32
#define Kcv 4
#define Rq 16
#define NC 2
#define ROWS (Bsz*Lq)   // 8192

// ---------------- scratch (static device globals; no allocations) -------------
// (padded by one extra row where the scan prefetches one step past the end)
__device__ __align__(16) float g_t0[ROWS*Dq];
__device__ __align__(16) float g_u[ROWS*Dq];
__device__ __align__(16) float g_xz[(ROWS+1)*2*DI];
__device__ __align__(16) float g_xi[(ROWS+1)*DI];
__device__ __align__(16) float g_dbc[(ROWS+1)*80];
__device__ __align__(16) float g_delta[(ROWS+1)*DI];
__device__ __align__(16) float g_y[ROWS*DI];
__device__ __align__(16) float g_weff[NC*DI];

// ---------------- packed f32x2 helpers ----------------------------------------
typedef unsigned long long ull;

__device__ __forceinline__ void ffma2(ull& d, ull a, ull b) {
    asm("fma.rn.f32x2 %0, %1, %2, %0;" : "+l"(d) : "l"(a), "l"(b));
}
__device__ __forceinline__ ull dup2(float x) {
    ull r;
    asm("mov.b64 %0, {%1, %1};" : "=l"(r) : "f"(x));
    return r;
}
__device__ __forceinline__ float lo32(ull v) { return __uint_as_float((unsigned)v); }
__device__ __forceinline__ float hi32(ull v) { return __uint_as_float((unsigned)(v >> 32)); }

// =======================================================================
// SGEMM: C(M,N) = A(M,K) * B(N,K)^T (+bias, EPI) — 128x128x8, 8x8/thread,
// double-buffered smem, FFMA2 packed math, quadrant fragments.
// M%128==0, K%8==0, N arbitrary. EPI: 0 none, 1 softplus
// =======================================================================
template<int EPI>
__global__ __launch_bounds__(256) void sgemm128(
    const float* __restrict__ A, int lda,
    const float* __restrict__ Bw,   // (N,K) row-major
    const float* __restrict__ bias, // length N or nullptr
    float* __restrict__ C, int ldc,
    int M, int N, int K)
{
    __shared__ __align__(16) float As[2][8][132];
    __shared__ __align__(16) float Bs[2][8][132];

    const int tid = threadIdx.x;
    const int m0 = blockIdx.y * 128;
    const int n0 = blockIdx.x * 128;

    // global loads: one float4 per thread per 8-k tile
    const int lrow = tid >> 1;
    const int lk   = (tid & 1) * 4;
    const float* Ap = A + (size_t)(m0 + lrow) * lda + lk;
    const bool  bval = (n0 + lrow) < N;
    const float* Bp = Bw + (size_t)(n0 + lrow) * K + lk;

    const int tx = tid & 15;
    const int ty = tid >> 4;

    ull accp[4][8];   // [row-pair][col]; pairs: p0=(ty*4+0,1) p1=(+2,3) p2=(+64,65) p3=(+66,67)
    #pragma unroll
    for (int p = 0; p < 4; p++)
        #pragma unroll
        for (int j = 0; j < 8; j++) accp[p][j] = 0ull;

    {
        float4 av = *(const float4*)Ap;
        float4 bv = bval ? *(const float4*)Bp : make_float4(0.f,0.f,0.f,0.f);
        As[0][lk+0][lrow] = av.x; As[0][lk+1][lrow] = av.y;
        As[0][lk+2][lrow] = av.z; As[0][lk+3][lrow] = av.w;
        Bs[0][lk+0][lrow] = bv.x; Bs[0][lk+1][lrow] = bv.y;
        Bs[0][lk+2][lrow] = bv.z; Bs[0][lk+3][lrow] = bv.w;
    }
    __syncthreads();

    int buf = 0;
    for (int k0 = 8; k0 <= K; k0 += 8) {
        float4 an, bn;
        const bool more = (k0 < K);
        if (more) {
            an = *(const float4*)(Ap + k0);
            bn = bval ? *(const float4*)(Bp + k0) : make_float4(0.f,0.f,0.f,0.f);
        }
        #pragma unroll
        for (int k = 0; k < 8; k++) {
            ulonglong2 a01 = *(const ulonglong2*)&As[buf][k][ty*4];
            ulonglong2 a23 = *(const ulonglong2*)&As[buf][k][ty*4+64];
            float4 b0 = *(const float4*)&Bs[buf][k][tx*4];
            float4 b1 = *(const float4*)&Bs[buf][k][tx*4+64];
            ull ap[4] = {a01.x, a01.y, a23.x, a23.y};
            ull bd[8] = {dup2(b0.x),dup2(b0.y),dup2(b0.z),dup2(b0.w),
                         dup2(b1.x),dup2(b1.y),dup2(b1.z),dup2(b1.w)};
            #pragma unroll
            for (int p = 0; p < 4; p++)
                #pragma unroll
                for (int j = 0; j < 8; j++)
                    ffma2(accp[p][j], ap[p], bd[j]);
        }
        if (more) {
            buf ^= 1;
            As[buf][lk+0][lrow] = an.x; As[buf][lk+1][lrow] = an.y;
            As[buf][lk+2][lrow] = an.z; As[buf][lk+3][lrow] = an.w;
            Bs[buf][lk+0][lrow] = bn.x; Bs[buf][lk+1][lrow] = bn.y;
            Bs[buf][lk+2][lrow] = bn.z; Bs[buf][lk+3][lrow] = bn.w;
            __syncthreads();
        }
    }

    // epilogue
    const int cbase0 = n0 + tx*4;
    const int cbase1 = n0 + tx*4 + 64;
    #pragma unroll
    for (int p = 0; p < 4; p++) {
        const int rbase = m0 + ty*4 + (p & 1)*2 + (p >> 1)*64;
        #pragma unroll
        for (int h = 0; h < 2; h++) {
            const int row = rbase + h;
            float v[8];
            #pragma unroll
            for (int j = 0; j < 8; j++)
                v[j] = h ? hi32(accp[p][j]) : lo32(accp[p][j]);
            #pragma unroll
            for (int g = 0; g < 2; g++) {
                const int col = g ? cbase1 : cbase0;
                float* cp = C + (size_t)row * ldc + col;
                float vv[4];
                #pragma unroll
                for (int j = 0; j < 4; j++) {
                    float t = v[g*4+j] + (bias ? __ldg(bias + col + j) : 0.f);
                    if (EPI == 1) t = fmaxf(t, 0.f) + log1pf(__expf(-fabsf(t)));
                    vv[j] = t;
                }
                if (col + 3 < N) {
                    *(float4*)cp = make_float4(vv[0], vv[1], vv[2], vv[3]);
                } else {
                    #pragma unroll
                    for (int j = 0; j < 4; j++)
                        if (col + j < N) cp[j] = vv[j];
                }
            }
        }
    }
}

// ---------------- LayerNorm (+relu) over D=256, block per row -----------------
__inline__ __device__ float warpSum(float v) {
    #pragma unroll
    for (int o = 16; o; o >>= 1) v += __shfl_xor_sync(0xffffffffu, v, o);
    return v;
}

__global__ __launch_bounds__(256) void ln_relu_kernel(
    const float* __restrict__ in, const float* __restrict__ gam,
    const float* __restrict__ bet, float* __restrict__ out)
{
    const int row = blockIdx.x, tid = threadIdx.x;
    const float v = in[(size_t)row * Dq + tid];
    float s = warpSum(v);
    float q = warpSum(v * v);
    __shared__ float ss[8], sq[8];
    if ((tid & 31) == 0) { ss[tid >> 5] = s; sq[tid >> 5] = q; }
    __syncthreads();
    float tot = 0.f, totq = 0.f;
    #pragma unroll
    for (int i = 0; i < 8; i++) { tot += ss[i]; totq += sq[i]; }
    const float mu  = tot * (1.f / Dq);
    const float var = totq * (1.f / Dq) - mu * mu;
    const float r   = rsqrtf(var + 1e-5f);
    float o = (v - mu) * r * gam[tid] + bet[tid];
    out[(size_t)row * Dq + tid] = fmaxf(o, 0.f);
}

// ---------------- depthwise causal conv K=4 + silu, 4 timesteps/thread --------
__global__ __launch_bounds__(256) void conv_silu_kernel(
    const float* __restrict__ xz, const float* __restrict__ cw,
    const float* __restrict__ cb, float* __restrict__ xi)
{
    const int idx = blockIdx.x * blockDim.x + threadIdx.x;
    const int d = idx & (DI - 1);
    const int rg = idx >> 9;
    const int t0 = (rg & 255) * 4;
    const int b  = rg >> 8;

    const float w0 = __ldg(cw + d*Kcv + 0);
    const float w1 = __ldg(cw + d*Kcv + 1);
    const float w2 = __ldg(cw + d*Kcv + 2);
    const float w3 = __ldg(cw + d*Kcv + 3);
    const float bb = __ldg(cb + d);

    const float* base = xz + (size_t)b * Lq * (2*DI) + d;
    float v[7];
    #pragma unroll
    for (int k = 0; k < 7; k++) {
        const int tt = t0 - 3 + k;
        v[k] = (tt >= 0) ? base[(size_t)tt * (2*DI)] : 0.f;
    }
    float* outp = xi + ((size_t)b * Lq + t0) * DI + d;
    #pragma unroll
    for (int j = 0; j < 4; j++) {
        float a = bb + w0*v[j] + w1*v[j+1] + w2*v[j+2] + w3*v[j+3];
        outp[(size_t)j * DI] = a / (1.f + __expf(-a));
    }
}

// ---------------- selective scan (software-pipelined loads) -------------------
__global__ __launch_bounds__(128) void scan_kernel(
    const float* __restrict__ delta, const float* __restrict__ dbc,
    const float* __restrict__ xi, const float* __restrict__ xz,
    const float* __restrict__ A_log, const float* __restrict__ D_param,
    float* __restrict__ y)
{
    const int w = blockIdx.x * 4 + (threadIdx.x >> 5);  // 0..1023
    const int lane = threadIdx.x & 31;
    const int b  = w >> 7;
    const int dg = w & 127;
    const int li = lane & 7;
    const int ci = lane >> 3;
    const int d  = dg * 4 + ci;

    const float LOG2E = 1.4426950408889634f;
    float Ac[4], h[4];
    #pragma unroll
    for (int j = 0; j < 4; j++) {
        Ac[j] = -__expf(A_log[d * Nst + li * 4 + j]) * LOG2E;
        h[j] = 0.f;
    }
    const float Dp = D_param[d];

    const size_t rowbase = (size_t)b * Lq;
    const float* pd = delta + rowbase * DI + d;
    const float* px = xi    + rowbase * DI + d;
    const float* pz = xz    + rowbase * (2*DI) + DI + d;
    const float* pb = dbc   + rowbase * 80 + Rq + li * 4;
    float*       py = y     + rowbase * DI + d;

    float dv = __ldg(pd), xv = __ldg(px), zv = __ldg(pz);
    float4 Bv = *(const float4*)pb;
    float4 Cv = *(const float4*)(pb + Nst);

    for (int t = 0; t < Lq; t++) {
        // prefetch t+1 (scratch arrays are padded by one row)
        pd += DI; px += DI; pz += 2*DI; pb += 80;
        const float dvn = __ldg(pd);
        const float xvn = __ldg(px);
        const float zvn = __ldg(pz);
        const float4 Bvn = *(const float4*)pb;
        const float4 Cvn = *(const float4*)(pb + Nst);

        const float dx = dv * xv;
        h[0] = exp2f(dv * Ac[0]) * h[0] + dx * Bv.x;
        h[1] = exp2f(dv * Ac[1]) * h[1] + dx * Bv.y;
        h[2] = exp2f(dv * Ac[2]) * h[2] + dx * Bv.z;
        h[3] = exp2f(dv * Ac[3]) * h[3] + dx * Bv.w;
        float acc = h[0]*Cv.x + h[1]*Cv.y + h[2]*Cv.z + h[3]*Cv.w;
        acc += __shfl_xor_sync(0xffffffffu, acc, 4);
        acc += __shfl_xor_sync(0xffffffffu, acc, 2);
        acc += __shfl_xor_sync(0xffffffffu, acc, 1);
        if (li == 0) {
            const float yv = acc + xv * Dp;
            const float sz = zv / (1.f + __expf(-zv));
            py[0] = yv * sz;
        }
        py += DI;
        dv = dvn; xv = xvn; zv = zvn; Bv = Bvn; Cv = Cvn;
    }
}

// ---------------- W_eff = W_out @ out_proj_w  (NC x DI) -----------------------
__global__ __launch_bounds__(256) void weff_kernel(
    const float* __restrict__ Wout, const float* __restrict__ opw,
    float* __restrict__ Weff)
{
    const int tid = blockIdx.x * blockDim.x + threadIdx.x; // < NC*DI
    const int c = tid >> 9;
    const int k = tid & (DI - 1);
    float acc = 0.f;
    #pragma unroll 8
    for (int dd = 0; dd < Dq; dd++)
        acc += Wout[c * Dq + dd] * opw[(size_t)dd * DI + k];
    Weff[tid] = acc;
}

// ---------------- head GEMV: logits = y @ Weff^T + b_out ----------------------
__global__ __launch_bounds__(256) void head_kernel(
    const float* __restrict__ y, const float* __restrict__ Weff,
    const float* __restrict__ bout, float* __restrict__ out)
{
    const int w = (blockIdx.x * blockDim.x + threadIdx.x) >> 5; // row
    const int lane = threadIdx.x & 31;
    float a0 = 0.f, a1 = 0.f;
    const float* yrow = y + (size_t)w * DI;
    #pragma unroll
    for (int k = lane*4; k < DI; k += 128) {
        const float4 yv = *(const float4*)(yrow + k);
        const float4 w0 = *(const float4*)(Weff + k);
        const float4 w1 = *(const float4*)(Weff + DI + k);
        a0 += yv.x*w0.x + yv.y*w0.y + yv.z*w0.z + yv.w*w0.w;
        a1 += yv.x*w1.x + yv.y*w1.y + yv.z*w1.z + yv.w*w1.w;
    }
    a0 = warpSum(a0);
    a1 = warpSum(a1);
    if (lane == 0) {
        out[(size_t)w * NC + 0] = a0 + bout[0];
        out[(size_t)w * NC + 1] = a1 + bout[1];
    }
}

// ---------------- launch ------------------------------------------------------
static float* symAddr(const void* symbol) {
    void* p = nullptr;
    cudaGetSymbolAddress(&p, symbol);
    return (float*)p;
}

extern "C" void kernel_launch(void* const* d_in, const int* in_sizes, int n_in,
                              void* d_out, int out_size)
{
    const float* x         = (const float*)d_in[0];
    const float* W1        = (const float*)d_in[1];
    const float* b1        = (const float*)d_in[2];
    const float* ln_g      = (const float*)d_in[3];
    const float* ln_b      = (const float*)d_in[4];
    const float* in_proj_w = (const float*)d_in[5];
    const float* conv_w    = (const float*)d_in[6];
    const float* conv_b    = (const float*)d_in[7];
    const float* x_proj_w  = (const float*)d_in[8];
    const float* dt_proj_w = (const float*)d_in[9];
    const float* dt_proj_b = (const float*)d_in[10];
    const float* A_log     = (const float*)d_in[11];
    const float* D_param   = (const float*)d_in[12];
    const float* out_proj_w= (const float*)d_in[13];
    const float* W_out     = (const float*)d_in[14];
    const float* b_out     = (const float*)d_in[15];
    float* out = (float*)d_out;

    float* t0    = symAddr(g_t0);
    float* u     = symAddr(g_u);
    float* xz    = symAddr(g_xz);
    float* xi    = symAddr(g_xi);
    float* dbc   = symAddr(g_dbc);
    float* delta = symAddr(g_delta);
    float* y     = symAddr(g_y);
    float* weff  = symAddr(g_weff);

    // 0) fold out_proj into the classifier head
    weff_kernel<<<(NC*DI)/256, 256>>>(W_out, out_proj_w, weff);
    // 1) fc1: t0 = x @ W1^T + b1
    sgemm128<0><<<dim3(Dq/128, ROWS/128), 256>>>(x, Fq, W1, b1, t0, Dq, ROWS, Dq, Fq);
    // 2) LN + relu -> u
    ln_relu_kernel<<<ROWS, Dq>>>(t0, ln_g, ln_b, u);
    // 3) in_proj: xz = u @ in_proj_w^T
    sgemm128<0><<<dim3((2*DI)/128, ROWS/128), 256>>>(u, Dq, in_proj_w, nullptr, xz, 2*DI, ROWS, 2*DI, Dq);
    // 4) depthwise conv + silu -> xi
    conv_silu_kernel<<<(ROWS*DI/4)/256, 256>>>(xz, conv_w, conv_b, xi);
    // 5) x_proj: dbc = xi @ x_proj_w^T  (N=80)
    sgemm128<0><<<dim3(1, ROWS/128), 256>>>(xi, DI, x_proj_w, nullptr, dbc, 80, ROWS, 80, DI);
    // 6) dt_proj + softplus
    sgemm128<1><<<dim3(DI/128, ROWS/128), 256>>>(dbc, 80, dt_proj_w, dt_proj_b, delta, DI, ROWS, DI, Rq);
    // 7) selective scan -> y (gated)
    scan_kernel<<<256, 128>>>(delta, dbc, xi, xz, A_log, D_param, y);
    // 8) head: logits = y @ Weff^T + b_out
    head_kernel<<<ROWS/8, 256>>>(y, weff, b_out, out);
}